// round 15
// baseline (speedup 1.0000x reference)
#include <cuda_runtime.h>
#include <cuda_bf16.h>
#include <cstdint>

#define Nn 50000
#define Nn2 50048
#define Ee 640000
#define DIM 128
#define NC 6

#define TSTRIDE 272                 // smem bytes per tile row (136 halves)
#define TILE_BYTES (128 * TSTRIDE)  // 34816
#define PQ_TILE (16 * TSTRIDE)      // 4352
#define SCAN_NB 98                  // ceil(50000/512)

typedef unsigned long long ull;

// ---------------- device scratch ----------------
__device__ float g_h[Nn * DIM];     // fp32 activations (final input)
__device__ float g_p[Nn * 8];
__device__ float g_q[Nn * 8];
__device__ int   g_rowptr[Nn + 1];
__device__ int   g_cnt[Nn];         // zero-init; self-restoring per launch
__device__ volatile int g_agg[SCAN_NB];  // block aggregate+1 (0 = not ready); zeroed in count
__device__ int   g_neigh[Ee];
// pre-split bf16 activations (rows >= Nn stay zero: never written)
__device__ __align__(16) __nv_bfloat16 g_xhi[Nn2 * DIM];
__device__ __align__(16) __nv_bfloat16 g_xlo[Nn2 * DIM];
__device__ __align__(16) __nv_bfloat16 g_x2hi[Nn2 * DIM];
__device__ __align__(16) __nv_bfloat16 g_x2lo[Nn2 * DIM];
__device__ __align__(16) __nv_bfloat16 g_Whi[8 * DIM * DIM];
__device__ __align__(16) __nv_bfloat16 g_Wlo[8 * DIM * DIM];
// classifier tile [16][128]: rows 0-5 = W_top cols, rows 8-13 = W_bot cols, rest 0
__device__ __align__(16) __nv_bfloat16 g_W3hi[16 * DIM];
__device__ __align__(16) __nv_bfloat16 g_W3lo[16 * DIM];

// ---------------- helpers ----------------
__device__ __forceinline__ uint32_t smem_u32(const void* p) {
    uint32_t a;
    asm("{ .reg .u64 t; cvta.to.shared.u64 t, %1; cvt.u32.u64 %0, t; }" : "=r"(a) : "l"(p));
    return a;
}
__device__ __forceinline__ void ldsm4(uint32_t* r, uint32_t addr) {
    asm volatile("ldmatrix.sync.aligned.m8n8.x4.shared.b16 {%0,%1,%2,%3}, [%4];"
                 : "=r"(r[0]), "=r"(r[1]), "=r"(r[2]), "=r"(r[3]) : "r"(addr));
}
__device__ __forceinline__ void mma16816(float* c, const uint32_t* a, const uint32_t* b) {
    asm volatile(
        "mma.sync.aligned.m16n8k16.row.col.f32.bf16.bf16.f32 "
        "{%0,%1,%2,%3}, {%4,%5,%6,%7}, {%8,%9}, {%0,%1,%2,%3};"
        : "+f"(c[0]), "+f"(c[1]), "+f"(c[2]), "+f"(c[3])
        : "r"(a[0]), "r"(a[1]), "r"(a[2]), "r"(a[3]), "r"(b[0]), "r"(b[1]));
}
__device__ __forceinline__ uint32_t pack_bf16(float a, float b, float* ra, float* rb) {
    __nv_bfloat16 ha = __float2bfloat16(a);
    __nv_bfloat16 hb = __float2bfloat16(b);
    *ra = a - __bfloat162float(ha);
    *rb = b - __bfloat162float(hb);
    unsigned short ua = *(unsigned short*)&ha, ub = *(unsigned short*)&hb;
    return (uint32_t)ua | ((uint32_t)ub << 16);
}
__device__ __forceinline__ uint32_t pack_bf16_rn(float a, float b) {
    __nv_bfloat162 p = __floats2bfloat162_rn(a, b);
    return *(uint32_t*)&p;
}

// ---------------- count: g_agg reset + degree count ----------------
__global__ void count_kernel(const int* __restrict__ ei) {
    int idx = blockIdx.x * blockDim.x + threadIdx.x;
    if (idx < SCAN_NB) g_agg[idx] = 0;
    if (idx < Ee / 4) {   // degree count (g_cnt zero by invariant)
        int4 d = __ldg((const int4*)(ei + Ee) + idx);
        atomicAdd(&g_cnt[d.x], 1);
        atomicAdd(&g_cnt[d.y], 1);
        atomicAdd(&g_cnt[d.z], 1);
        atomicAdd(&g_cnt[d.w], 1);
    }
}

// ---------------- single-pass scan (value-as-flag lookback; all 98 blocks co-resident) ----------------
__global__ void scan_kernel() {
    __shared__ int ws[16];
    __shared__ int ws2[4];
    __shared__ int s_off;
    int tid = threadIdx.x, lane = tid & 31, w = tid >> 5;
    int b = blockIdx.x;
    int i = b * 512 + tid;
    int v = (i < Nn) ? g_cnt[i] : 0;
    int x = v;
    #pragma unroll
    for (int off = 1; off < 32; off <<= 1) {
        int y = __shfl_up_sync(0xffffffffu, x, off);
        if (lane >= off) x += y;
    }
    if (lane == 31) ws[w] = x;
    __syncthreads();
    if (w == 0) {
        int t = (lane < 16) ? ws[lane] : 0;
        #pragma unroll
        for (int off = 1; off < 16; off <<= 1) {
            int y = __shfl_up_sync(0xffffffffu, t, off);
            if (lane >= off) t += y;
        }
        if (lane < 16) ws[lane] = t;
    }
    __syncthreads();
    // publish aggregate (value doubles as ready flag: total+1 >= 1)
    if (tid == 0) atomicExch((int*)&g_agg[b], ws[15] + 1);
    // lookback: sum aggregates of all predecessor blocks
    if (tid < 128) {
        int val = 0;
        if (tid < b) {
            int t;
            do { t = g_agg[tid]; } while (t == 0);
            val = t - 1;
        }
        #pragma unroll
        for (int off = 16; off > 0; off >>= 1)
            val += __shfl_xor_sync(0xffffffffu, val, off);
        if (lane == 0) ws2[w] = val;
    }
    __syncthreads();
    if (tid == 0) s_off = ws2[0] + ws2[1] + ws2[2] + ws2[3];
    __syncthreads();
    int excl = (w ? ws[w - 1] : 0) + x - v;
    if (i < Nn) g_rowptr[i] = s_off + excl;
    if (b == 0 && tid == 0) g_rowptr[Nn] = Ee;
}

// ---------------- scatter (4 edges/thread, int4 index loads) + piggybacked weight prep ----------------
__global__ void scatter_kernel(const int* __restrict__ ei,
                               const float* w0, const float* w1, const float* w2,
                               const float* w3, const float* w4, const float* w5,
                               const float* w6, const float* w7, const float* clsW) {
    int idx = blockIdx.x * blockDim.x + threadIdx.x;

    // piggyback: classifier tile (first 2048 threads)
    if (idx < 16 * DIM) {
        int n = idx >> 7, k = idx & 127;
        float v = 0.f;
        if (n < 6) v = clsW[k * NC + n];
        else if (n >= 8 && n < 14) v = clsW[(128 + k) * NC + (n - 8)];
        __nv_bfloat16 h = __float2bfloat16(v);
        g_W3hi[idx] = h;
        g_W3lo[idx] = __float2bfloat16(v - __bfloat162float(h));
    }
    // piggyback: weight split/transpose (first 131072 threads)
    if (idx < 8 * DIM * DIM) {
        const float* ws[8] = {w0, w1, w2, w3, w4, w5, w6, w7};
        int g = idx >> 14, e = idx & 16383;
        int n = e >> 7, k = e & 127;
        float v = ws[g][k * DIM + n];
        __nv_bfloat16 h = __float2bfloat16(v);
        g_Whi[g * 16384 + e] = h;
        g_Wlo[g * 16384 + e] = __float2bfloat16(v - __bfloat162float(h));
    }

    // scatter proper: 4 edges per thread
    if (idx < Ee / 4) {
        int4 s = __ldg((const int4*)ei + idx);
        int4 d = __ldg((const int4*)(ei + Ee) + idx);
        int t0 = atomicSub(&g_cnt[d.x], 1) - 1;
        int t1 = atomicSub(&g_cnt[d.y], 1) - 1;
        int t2 = atomicSub(&g_cnt[d.z], 1) - 1;
        int t3 = atomicSub(&g_cnt[d.w], 1) - 1;
        g_neigh[g_rowptr[d.x] + t0] = s.x;
        g_neigh[g_rowptr[d.y] + t1] = s.y;
        g_neigh[g_rowptr[d.z] + t2] = s.z;
        g_neigh[g_rowptr[d.w] + t3] = s.w;
    }
}

// ---------------- aggregation: (xhi,xlo) = split(h[i] + sum_{j->i} h[j]), 8 loads in flight ----------------
__global__ void agg_kernel(const float* __restrict__ hin,
                           __nv_bfloat16* __restrict__ xhi,
                           __nv_bfloat16* __restrict__ xlo) {
    int w = (blockIdx.x * blockDim.x + threadIdx.x) >> 5;
    int lane = threadIdx.x & 31;
    if (w >= Nn) return;
    const float4* hp = (const float4*)hin;
    float4 a = __ldg(&hp[(size_t)w * 32 + lane]);
    float x0 = a.x, x1 = a.y, x2 = a.z, x3 = a.w;
    int beg = g_rowptr[w], end = g_rowptr[w + 1];
    int e = beg;
    for (; e + 7 < end; e += 8) {
        int j0 = g_neigh[e],     j1 = g_neigh[e + 1];
        int j2 = g_neigh[e + 2], j3 = g_neigh[e + 3];
        int j4 = g_neigh[e + 4], j5 = g_neigh[e + 5];
        int j6 = g_neigh[e + 6], j7 = g_neigh[e + 7];
        float4 v0 = __ldg(&hp[(size_t)j0 * 32 + lane]);
        float4 v1 = __ldg(&hp[(size_t)j1 * 32 + lane]);
        float4 v2 = __ldg(&hp[(size_t)j2 * 32 + lane]);
        float4 v3 = __ldg(&hp[(size_t)j3 * 32 + lane]);
        float4 v4 = __ldg(&hp[(size_t)j4 * 32 + lane]);
        float4 v5 = __ldg(&hp[(size_t)j5 * 32 + lane]);
        float4 v6 = __ldg(&hp[(size_t)j6 * 32 + lane]);
        float4 v7 = __ldg(&hp[(size_t)j7 * 32 + lane]);
        x0 += (v0.x + v1.x) + (v2.x + v3.x) + (v4.x + v5.x) + (v6.x + v7.x);
        x1 += (v0.y + v1.y) + (v2.y + v3.y) + (v4.y + v5.y) + (v6.y + v7.y);
        x2 += (v0.z + v1.z) + (v2.z + v3.z) + (v4.z + v5.z) + (v6.z + v7.z);
        x3 += (v0.w + v1.w) + (v2.w + v3.w) + (v4.w + v5.w) + (v6.w + v7.w);
    }
    for (; e + 1 < end; e += 2) {
        int j0 = g_neigh[e], j1 = g_neigh[e + 1];
        float4 v0 = __ldg(&hp[(size_t)j0 * 32 + lane]);
        float4 v1 = __ldg(&hp[(size_t)j1 * 32 + lane]);
        x0 += v0.x + v1.x; x1 += v0.y + v1.y;
        x2 += v0.z + v1.z; x3 += v0.w + v1.w;
    }
    if (e < end) {
        int j = g_neigh[e];
        float4 v = __ldg(&hp[(size_t)j * 32 + lane]);
        x0 += v.x; x1 += v.y; x2 += v.z; x3 += v.w;
    }
    float r0, r1, r2, r3;
    uint2 hw, lw;
    hw.x = pack_bf16(x0, x1, &r0, &r1);
    hw.y = pack_bf16(x2, x3, &r2, &r3);
    lw.x = pack_bf16_rn(r0, r1);
    lw.y = pack_bf16_rn(r2, r3);
    size_t off = (size_t)w * DIM + lane * 4;
    *(uint2*)(xhi + off) = hw;
    *(uint2*)(xlo + off) = lw;
}

// ---------------- fused dual-GEMM MLP (+ optional classifier MMA pass) ----------------
// MODE1 0: epilogue1 = BN+ReLU; 1: bias+ReLU.
// OUTBF 0: epilogue2 -> fp32 Hout; 1: -> split bf16 (Ohi/Olo).
// PQ 1: after epilogue2, run N=16 classifier MMA on final H, emit g_p/g_q.
template <int MODE1, int OUTBF, int PQ>
__global__ __launch_bounds__(512, 1) void fused_mlp(
    const __nv_bfloat16* __restrict__ Ahi_g, const __nv_bfloat16* __restrict__ Alo_g,
    const __nv_bfloat16* __restrict__ B1h, const __nv_bfloat16* __restrict__ B1l,
    const __nv_bfloat16* __restrict__ B2h, const __nv_bfloat16* __restrict__ B2l,
    const float* __restrict__ b1, const float* __restrict__ gg,
    const float* __restrict__ be, const float* __restrict__ rm,
    const float* __restrict__ rv, const float* __restrict__ b2,
    const float* __restrict__ clsb,
    float* __restrict__ Hout, __nv_bfloat16* __restrict__ Ohi,
    __nv_bfloat16* __restrict__ Olo, int M, int ntiles)
{
    extern __shared__ __align__(16) char dyn[];
    __shared__ float s_sc[DIM], s_sh[DIM], s_b2[DIM], s_cb[8];

    const int tid = threadIdx.x, lane = tid & 31, wid = tid >> 5;
    const uint32_t sbase = smem_u32(dyn);

    if (tid < DIM) {
        int c = tid;
        if (MODE1 == 0) {
            float s = gg[c] * rsqrtf(rv[c] + 1e-5f);
            s_sc[c] = s;
            s_sh[c] = (b1[c] - rm[c]) * s + be[c];
        } else {
            s_sc[c] = 1.0f;
            s_sh[c] = b1[c];
        }
        s_b2[c] = b2[c];
    }
    if (PQ && tid < 8) s_cb[tid] = (tid < 6) ? clsb[tid] : 0.f;

    {   // weight tiles once (persistent block)
        const uint4* p1h = (const uint4*)B1h;
        const uint4* p1l = (const uint4*)B1l;
        const uint4* p2h = (const uint4*)B2h;
        const uint4* p2l = (const uint4*)B2l;
        #pragma unroll
        for (int it = 0; it < 4; it++) {
            int i = tid + it * 512;
            uint32_t so = (uint32_t)(i >> 4) * TSTRIDE + (i & 15) * 16;
            *(uint4*)(dyn + 2 * TILE_BYTES + so) = __ldg(p1h + i);
            *(uint4*)(dyn + 3 * TILE_BYTES + so) = __ldg(p1l + i);
            *(uint4*)(dyn + 4 * TILE_BYTES + so) = __ldg(p2h + i);
            *(uint4*)(dyn + 5 * TILE_BYTES + so) = __ldg(p2l + i);
        }
        if (PQ && tid < 256) {   // classifier tile 16x128 bf16 hi/lo
            uint32_t so = (uint32_t)(tid >> 4) * TSTRIDE + (tid & 15) * 16;
            *(uint4*)(dyn + 6 * TILE_BYTES + so) = __ldg((const uint4*)g_W3hi + tid);
            *(uint4*)(dyn + 6 * TILE_BYTES + PQ_TILE + so) = __ldg((const uint4*)g_W3lo + tid);
        }
    }

    const int wm = wid >> 2, wn = wid & 3;
    const uint32_t aAddr = sbase + (uint32_t)(wm * 32 + (lane & 15)) * TSTRIDE + (lane >> 4) * 16;
    // B via ldsm4: lanes 0-7 -> [n0-7,klo], 8-15 -> [n0-7,khi], 16-23 -> [n8-15,klo], 24-31 -> [n8-15,khi]
    const int quad = lane >> 3;
    const uint32_t bRow = (uint32_t)((quad >> 1) * 8 + (lane & 7));
    const uint32_t bCol = (uint32_t)((quad & 1) * 16);
    const uint32_t bAddr1 = sbase + 2 * TILE_BYTES +
                            ((uint32_t)wn * 32 + bRow) * TSTRIDE + bCol;
    const uint32_t bAddr2 = bAddr1 + 2 * TILE_BYTES;
    const uint32_t bAddr3 = sbase + 6 * TILE_BYTES + bRow * TSTRIDE + bCol;
    const int g4 = lane >> 2, tig = lane & 3;
    // PQ warps: one per SMSP, one per wm band: wid 0,5,10,15
    const bool pqWarp = PQ && ((wid & 3) == (wid >> 2));

    for (int t = blockIdx.x; t < ntiles; t += gridDim.x) {
        int row0 = t * 128;
        __syncthreads();   // prior-tile readers of A smem done

        {   // A tiles: straight uint4 copies
            const uint4* ah4 = (const uint4*)(Ahi_g + (size_t)row0 * DIM);
            const uint4* al4 = (const uint4*)(Alo_g + (size_t)row0 * DIM);
            #pragma unroll
            for (int it = 0; it < 4; it++) {
                int i = tid + it * 512;
                uint32_t so = (uint32_t)(i >> 4) * TSTRIDE + (i & 15) * 16;
                *(uint4*)(dyn + so) = __ldg(ah4 + i);
                *(uint4*)(dyn + TILE_BYTES + so) = __ldg(al4 + i);
            }
        }
        __syncthreads();

        // ---- MMA pass 1 ----
        float acc[2][4][4];
        #pragma unroll
        for (int ma = 0; ma < 2; ma++)
            #pragma unroll
            for (int na = 0; na < 4; na++)
                #pragma unroll
                for (int q = 0; q < 4; q++) acc[ma][na][q] = 0.f;

        #pragma unroll
        for (int ks = 0; ks < 8; ks++) {
            uint32_t kb = ks * 32;
            uint32_t ah[2][4], al[2][4], bh[2][4], bl[2][4];
            ldsm4(ah[0], aAddr + kb);
            ldsm4(ah[1], aAddr + 16 * TSTRIDE + kb);
            ldsm4(al[0], aAddr + TILE_BYTES + kb);
            ldsm4(al[1], aAddr + TILE_BYTES + 16 * TSTRIDE + kb);
            ldsm4(bh[0], bAddr1 + kb);                         // n0-15: {r0,r1},{r2,r3}
            ldsm4(bh[1], bAddr1 + 16 * TSTRIDE + kb);          // n16-31
            ldsm4(bl[0], bAddr1 + TILE_BYTES + kb);
            ldsm4(bl[1], bAddr1 + TILE_BYTES + 16 * TSTRIDE + kb);
            #pragma unroll
            for (int ma = 0; ma < 2; ma++)
                #pragma unroll
                for (int na = 0; na < 4; na++) {
                    const uint32_t* pbh = &bh[na >> 1][(na & 1) * 2];
                    const uint32_t* pbl = &bl[na >> 1][(na & 1) * 2];
                    mma16816(acc[ma][na], ah[ma], pbh);
                    mma16816(acc[ma][na], ah[ma], pbl);
                    mma16816(acc[ma][na], al[ma], pbh);
                }
        }
        __syncthreads();   // all warps done reading A tile

        // epilogue 1: scale/shift + ReLU, split, Z -> A smem
        #pragma unroll
        for (int ma = 0; ma < 2; ma++) {
            int lr1 = wm * 32 + ma * 16 + g4;
            int lr2 = lr1 + 8;
            #pragma unroll
            for (int na = 0; na < 4; na++) {
                int col = wn * 32 + na * 8 + 2 * tig;
                float sc0 = s_sc[col], sc1 = s_sc[col + 1];
                float sh0 = s_sh[col], sh1 = s_sh[col + 1];
                float o0 = fmaxf(fmaf(acc[ma][na][0], sc0, sh0), 0.f);
                float o1 = fmaxf(fmaf(acc[ma][na][1], sc1, sh1), 0.f);
                float o2 = fmaxf(fmaf(acc[ma][na][2], sc0, sh0), 0.f);
                float o3 = fmaxf(fmaf(acc[ma][na][3], sc1, sh1), 0.f);
                float q0, q1;
                uint32_t so1 = (uint32_t)lr1 * TSTRIDE + col * 2;
                uint32_t so2 = (uint32_t)lr2 * TSTRIDE + col * 2;
                *(uint32_t*)(dyn + so1) = pack_bf16(o0, o1, &q0, &q1);
                *(uint32_t*)(dyn + TILE_BYTES + so1) = pack_bf16_rn(q0, q1);
                *(uint32_t*)(dyn + so2) = pack_bf16(o2, o3, &q0, &q1);
                *(uint32_t*)(dyn + TILE_BYTES + so2) = pack_bf16_rn(q0, q1);
            }
        }
        __syncthreads();

        // ---- MMA pass 2 ----
        #pragma unroll
        for (int ma = 0; ma < 2; ma++)
            #pragma unroll
            for (int na = 0; na < 4; na++)
                #pragma unroll
                for (int q = 0; q < 4; q++) acc[ma][na][q] = 0.f;

        #pragma unroll
        for (int ks = 0; ks < 8; ks++) {
            uint32_t kb = ks * 32;
            uint32_t ah[2][4], al[2][4], bh[2][4], bl[2][4];
            ldsm4(ah[0], aAddr + kb);
            ldsm4(ah[1], aAddr + 16 * TSTRIDE + kb);
            ldsm4(al[0], aAddr + TILE_BYTES + kb);
            ldsm4(al[1], aAddr + TILE_BYTES + 16 * TSTRIDE + kb);
            ldsm4(bh[0], bAddr2 + kb);
            ldsm4(bh[1], bAddr2 + 16 * TSTRIDE + kb);
            ldsm4(bl[0], bAddr2 + TILE_BYTES + kb);
            ldsm4(bl[1], bAddr2 + TILE_BYTES + 16 * TSTRIDE + kb);
            #pragma unroll
            for (int ma = 0; ma < 2; ma++)
                #pragma unroll
                for (int na = 0; na < 4; na++) {
                    const uint32_t* pbh = &bh[na >> 1][(na & 1) * 2];
                    const uint32_t* pbl = &bl[na >> 1][(na & 1) * 2];
                    mma16816(acc[ma][na], ah[ma], pbh);
                    mma16816(acc[ma][na], ah[ma], pbl);
                    mma16816(acc[ma][na], al[ma], pbh);
                }
        }
        if (PQ) __syncthreads();   // all warps done reading Z before H-split overwrites it

        // epilogue 2: bias + ReLU -> fp32 / split bf16; PQ: also H-split -> A smem
        #pragma unroll
        for (int ma = 0; ma < 2; ma++) {
            int r1 = row0 + wm * 32 + ma * 16 + g4;
            int r2 = r1 + 8;
            int lr1 = wm * 32 + ma * 16 + g4;
            int lr2 = lr1 + 8;
            #pragma unroll
            for (int na = 0; na < 4; na++) {
                int col = wn * 32 + na * 8 + 2 * tig;
                float sh0 = s_b2[col], sh1 = s_b2[col + 1];
                float o0 = fmaxf(acc[ma][na][0] + sh0, 0.f);
                float o1 = fmaxf(acc[ma][na][1] + sh1, 0.f);
                float o2 = fmaxf(acc[ma][na][2] + sh0, 0.f);
                float o3 = fmaxf(acc[ma][na][3] + sh1, 0.f);
                if (PQ) {
                    float q0, q1;
                    uint32_t so1 = (uint32_t)lr1 * TSTRIDE + col * 2;
                    uint32_t so2 = (uint32_t)lr2 * TSTRIDE + col * 2;
                    *(uint32_t*)(dyn + so1) = pack_bf16(o0, o1, &q0, &q1);
                    *(uint32_t*)(dyn + TILE_BYTES + so1) = pack_bf16_rn(q0, q1);
                    *(uint32_t*)(dyn + so2) = pack_bf16(o2, o3, &q0, &q1);
                    *(uint32_t*)(dyn + TILE_BYTES + so2) = pack_bf16_rn(q0, q1);
                }
                if (OUTBF) {
                    if (r1 < M) {
                        float q0, q1;
                        *(uint32_t*)(Ohi + (size_t)r1 * DIM + col) = pack_bf16(o0, o1, &q0, &q1);
                        *(uint32_t*)(Olo + (size_t)r1 * DIM + col) = pack_bf16_rn(q0, q1);
                    }
                    if (r2 < M) {
                        float q0, q1;
                        *(uint32_t*)(Ohi + (size_t)r2 * DIM + col) = pack_bf16(o2, o3, &q0, &q1);
                        *(uint32_t*)(Olo + (size_t)r2 * DIM + col) = pack_bf16_rn(q0, q1);
                    }
                } else {
                    if (r1 < M) *(float2*)(Hout + (size_t)r1 * DIM + col) = make_float2(o0, o1);
                    if (r2 < M) *(float2*)(Hout + (size_t)r2 * DIM + col) = make_float2(o2, o3);
                }
            }
        }

        if (PQ) {
            __syncthreads();   // H-split visible
            if (pqWarp) {
                float acc3[2][2][4];
                #pragma unroll
                for (int ma = 0; ma < 2; ma++)
                    #pragma unroll
                    for (int na = 0; na < 2; na++)
                        #pragma unroll
                        for (int q = 0; q < 4; q++) acc3[ma][na][q] = 0.f;
                #pragma unroll
                for (int ks = 0; ks < 8; ks++) {
                    uint32_t kb = ks * 32;
                    uint32_t ah[2][4], al[2][4], b3h[4], b3l[4];
                    ldsm4(ah[0], aAddr + kb);
                    ldsm4(ah[1], aAddr + 16 * TSTRIDE + kb);
                    ldsm4(al[0], aAddr + TILE_BYTES + kb);
                    ldsm4(al[1], aAddr + TILE_BYTES + 16 * TSTRIDE + kb);
                    ldsm4(b3h, bAddr3 + kb);            // {r0,r1}=p rows, {r2,r3}=q rows
                    ldsm4(b3l, bAddr3 + PQ_TILE + kb);
                    #pragma unroll
                    for (int ma = 0; ma < 2; ma++)
                        #pragma unroll
                        for (int na = 0; na < 2; na++) {
                            const uint32_t* pbh = &b3h[na * 2];
                            const uint32_t* pbl = &b3l[na * 2];
                            mma16816(acc3[ma][na], ah[ma], pbh);
                            mma16816(acc3[ma][na], ah[ma], pbl);
                            mma16816(acc3[ma][na], al[ma], pbh);
                        }
                }
                // emit p (na=0, +bias) and q (na=1)
                #pragma unroll
                for (int ma = 0; ma < 2; ma++) {
                    int r1 = row0 + wm * 32 + ma * 16 + g4;
                    int r2 = r1 + 8;
                    int c0 = 2 * tig;
                    if (r1 < M) {
                        *(float2*)(g_p + (size_t)r1 * 8 + c0) =
                            make_float2(acc3[ma][0][0] + s_cb[c0], acc3[ma][0][1] + s_cb[c0 + 1]);
                        *(float2*)(g_q + (size_t)r1 * 8 + c0) =
                            make_float2(acc3[ma][1][0], acc3[ma][1][1]);
                    }
                    if (r2 < M) {
                        *(float2*)(g_p + (size_t)r2 * 8 + c0) =
                            make_float2(acc3[ma][0][2] + s_cb[c0], acc3[ma][0][3] + s_cb[c0 + 1]);
                        *(float2*)(g_q + (size_t)r2 * 8 + c0) =
                            make_float2(acc3[ma][1][2], acc3[ma][1][3]);
                    }
                }
            }
        }
    }
}

// ---------------- final: 8 edges per warp (MLP=16 row loads, 8KB contiguous stores) ----------------
__global__ void final_kernel(const float* __restrict__ h, const int* __restrict__ ei,
                             float* __restrict__ out0, float* __restrict__ eout) {
    int w = (blockIdx.x * blockDim.x + threadIdx.x) >> 5;
    int lane = threadIdx.x & 31;
    int e0 = w << 3;
    if (e0 >= Ee) return;
    const float4* hp = (const float4*)h;
    int s[8], d[8];
    #pragma unroll
    for (int i = 0; i < 8; i++) {
        s[i] = __ldg(ei + e0 + i);
        d[i] = __ldg(ei + Ee + e0 + i);
    }
    float4 av[8], bv[8];
    #pragma unroll
    for (int i = 0; i < 8; i++) {
        av[i] = __ldg(&hp[(size_t)s[i] * 32 + lane]);
        bv[i] = __ldg(&hp[(size_t)d[i] * 32 + lane]);
    }
    float4* ep = (float4*)(eout + (size_t)e0 * 256);
    #pragma unroll
    for (int i = 0; i < 8; i++) {
        __stcs(&ep[i * 64 + lane], av[i]);
        __stcs(&ep[i * 64 + 32 + lane], bv[i]);
    }
    if (lane < NC) {
        #pragma unroll
        for (int i = 0; i < 8; i++)
            __stcs(&out0[(size_t)(e0 + i) * NC + lane],
                   g_p[s[i] * 8 + lane] + g_q[d[i] * 8 + lane]);
    }
}

// ---------------- launch ----------------
extern "C" void kernel_launch(void* const* d_in, const int* in_sizes, int n_in,
                              void* d_out, int out_size) {
    const float* x     = (const float*)d_in[0];
    const int*   ei    = (const int*)d_in[1];
    const float* c1_W1 = (const float*)d_in[3];
    const float* c1_b1 = (const float*)d_in[4];
    const float* c1_g  = (const float*)d_in[5];
    const float* c1_be = (const float*)d_in[6];
    const float* c1_rm = (const float*)d_in[7];
    const float* c1_rv = (const float*)d_in[8];
    const float* c1_W2 = (const float*)d_in[9];
    const float* c1_b2 = (const float*)d_in[10];
    const float* cv_W1 = (const float*)d_in[11];
    const float* cv_b1 = (const float*)d_in[12];
    const float* cv_g  = (const float*)d_in[13];
    const float* cv_be = (const float*)d_in[14];
    const float* cv_rm = (const float*)d_in[15];
    const float* cv_rv = (const float*)d_in[16];
    const float* cv_W2 = (const float*)d_in[17];
    const float* cv_b2 = (const float*)d_in[18];
    const float* lin_W = (const float*)d_in[19];
    const float* lin_b = (const float*)d_in[20];
    const float* cls_W = (const float*)d_in[21];
    const float* cls_b = (const float*)d_in[22];

    float* out0 = (float*)d_out;
    float* eout = out0 + (size_t)Ee * NC;

    void *ph, *pxh, *pxl, *px2h, *px2l, *pwh, *pwl;
    cudaGetSymbolAddress(&ph, g_h);
    cudaGetSymbolAddress(&pxh, g_xhi);
    cudaGetSymbolAddress(&pxl, g_xlo);
    cudaGetSymbolAddress(&px2h, g_x2hi);
    cudaGetSymbolAddress(&px2l, g_x2lo);
    cudaGetSymbolAddress(&pwh, g_Whi);
    cudaGetSymbolAddress(&pwl, g_Wlo);
    float* H = (float*)ph;
    __nv_bfloat16* XH = (__nv_bfloat16*)pxh;
    __nv_bfloat16* XL = (__nv_bfloat16*)pxl;
    __nv_bfloat16* X2H = (__nv_bfloat16*)px2h;
    __nv_bfloat16* X2L = (__nv_bfloat16*)px2l;
    const __nv_bfloat16* WH = (const __nv_bfloat16*)pwh;
    const __nv_bfloat16* WL = (const __nv_bfloat16*)pwl;

    const int NT = Nn2 / 128;                 // 391 tiles
    const int GG = 148;
    const int AGG_B = (Nn * 32 + 255) / 256;          // 1 node per warp
    const int FIN_B = ((Ee / 8) * 32 + 511) / 512;    // 8 edges per warp, 512-thr blocks
    const int SMEM_F  = 6 * TILE_BYTES;               // 208896
    const int SMEM_FP = 6 * TILE_BYTES + 2 * PQ_TILE; // 217600

    cudaFuncSetAttribute(fused_mlp<0, 0, 0>, cudaFuncAttributeMaxDynamicSharedMemorySize, SMEM_F);
    cudaFuncSetAttribute(fused_mlp<0, 1, 0>, cudaFuncAttributeMaxDynamicSharedMemorySize, SMEM_F);
    cudaFuncSetAttribute(fused_mlp<1, 0, 1>, cudaFuncAttributeMaxDynamicSharedMemorySize, SMEM_FP);

    // CSR build; weight prep piggybacked on scatter
    count_kernel<<<625, 256>>>(ei);
    scan_kernel<<<SCAN_NB, 512>>>();
    scatter_kernel<<<625, 256>>>(ei, c1_W1, c1_W2,
                                 cv_W1, cv_W1 + DIM * DIM,
                                 cv_W2, cv_W2 + DIM * DIM,
                                 lin_W, lin_W + DIM * DIM, cls_W);
    // slots: 0=c1_W1 1=c1_W2 2=cvW1[0] 3=cvW1[1] 4=cvW2[0] 5=cvW2[1] 6=linW[0] 7=linW[1]

    // GIN1: agg(x) -> X; MLP(X) -> H
    agg_kernel<<<AGG_B, 256>>>(x, XH, XL);
    fused_mlp<0, 0, 0><<<GG, 512, SMEM_F>>>(XH, XL, WH + 0 * 16384, WL + 0 * 16384,
                                            WH + 1 * 16384, WL + 1 * 16384,
                                            c1_b1, c1_g, c1_be, c1_rm, c1_rv, c1_b2, 0,
                                            H, 0, 0, Nn, NT);
    // GIN2
    agg_kernel<<<AGG_B, 256>>>(H, XH, XL);
    fused_mlp<0, 0, 0><<<GG, 512, SMEM_F>>>(XH, XL, WH + 2 * 16384, WL + 2 * 16384,
                                            WH + 4 * 16384, WL + 4 * 16384,
                                            cv_b1, cv_g, cv_be, cv_rm, cv_rv, cv_b2, 0,
                                            H, 0, 0, Nn, NT);
    // GIN3 -> split X2
    agg_kernel<<<AGG_B, 256>>>(H, XH, XL);
    fused_mlp<0, 1, 0><<<GG, 512, SMEM_F>>>(XH, XL, WH + 3 * 16384, WL + 3 * 16384,
                                            WH + 5 * 16384, WL + 5 * 16384,
                                            cv_b1 + DIM, cv_g + DIM, cv_be + DIM,
                                            cv_rm + DIM, cv_rv + DIM, cv_b2 + DIM, 0,
                                            0, X2H, X2L, Nn, NT);
    // linear layers + fused classifier: MLP(X2) -> H, p, q
    fused_mlp<1, 0, 1><<<GG, 512, SMEM_FP>>>(X2H, X2L, WH + 6 * 16384, WL + 6 * 16384,
                                             WH + 7 * 16384, WL + 7 * 16384,
                                             lin_b, 0, 0, 0, 0, lin_b + DIM, cls_b,
                                             H, 0, 0, Nn, NT);

    // edge output (edge-ordered, 8 edges/warp)
    final_kernel<<<FIN_B, 512>>>(H, ei, out0, eout);
}

// round 16
// speedup vs baseline: 1.0161x; 1.0161x over previous
#include <cuda_runtime.h>
#include <cuda_bf16.h>
#include <cstdint>

#define Nn 50000
#define Nn2 50048
#define Ee 640000
#define DIM 128
#define NC 6

#define TSTRIDE 272                 // smem bytes per tile row (136 halves)
#define TILE_BYTES (128 * TSTRIDE)  // 34816
#define PQ_TILE (16 * TSTRIDE)      // 4352
#define SCAN_NB 98                  // ceil(50000/512)

typedef unsigned long long ull;

// ---------------- device scratch ----------------
__device__ float g_h[Nn * DIM];     // fp32 activations (final input)
__device__ float g_p[Nn * 8];
__device__ float g_q[Nn * 8];
__device__ int   g_rowptr[Nn + 1];
__device__ int   g_cnt[Nn];         // zero-init; self-restoring per launch
__device__ volatile int g_agg[SCAN_NB];  // block aggregate+1 (0 = not ready); zeroed in count
__device__ int   g_neigh[Ee];
// pre-split bf16 activations (rows >= Nn stay zero: never written)
__device__ __align__(16) __nv_bfloat16 g_xhi[Nn2 * DIM];
__device__ __align__(16) __nv_bfloat16 g_xlo[Nn2 * DIM];
__device__ __align__(16) __nv_bfloat16 g_x2hi[Nn2 * DIM];
__device__ __align__(16) __nv_bfloat16 g_x2lo[Nn2 * DIM];
__device__ __align__(16) __nv_bfloat16 g_Whi[8 * DIM * DIM];
__device__ __align__(16) __nv_bfloat16 g_Wlo[8 * DIM * DIM];
// classifier tile [16][128]: rows 0-5 = W_top cols, rows 8-13 = W_bot cols, rest 0
__device__ __align__(16) __nv_bfloat16 g_W3hi[16 * DIM];
__device__ __align__(16) __nv_bfloat16 g_W3lo[16 * DIM];

// ---------------- helpers ----------------
__device__ __forceinline__ uint32_t smem_u32(const void* p) {
    uint32_t a;
    asm("{ .reg .u64 t; cvta.to.shared.u64 t, %1; cvt.u32.u64 %0, t; }" : "=r"(a) : "l"(p));
    return a;
}
__device__ __forceinline__ void ldsm4(uint32_t* r, uint32_t addr) {
    asm volatile("ldmatrix.sync.aligned.m8n8.x4.shared.b16 {%0,%1,%2,%3}, [%4];"
                 : "=r"(r[0]), "=r"(r[1]), "=r"(r[2]), "=r"(r[3]) : "r"(addr));
}
__device__ __forceinline__ void mma16816(float* c, const uint32_t* a, const uint32_t* b) {
    asm volatile(
        "mma.sync.aligned.m16n8k16.row.col.f32.bf16.bf16.f32 "
        "{%0,%1,%2,%3}, {%4,%5,%6,%7}, {%8,%9}, {%0,%1,%2,%3};"
        : "+f"(c[0]), "+f"(c[1]), "+f"(c[2]), "+f"(c[3])
        : "r"(a[0]), "r"(a[1]), "r"(a[2]), "r"(a[3]), "r"(b[0]), "r"(b[1]));
}
__device__ __forceinline__ uint32_t pack_bf16(float a, float b, float* ra, float* rb) {
    __nv_bfloat16 ha = __float2bfloat16(a);
    __nv_bfloat16 hb = __float2bfloat16(b);
    *ra = a - __bfloat162float(ha);
    *rb = b - __bfloat162float(hb);
    unsigned short ua = *(unsigned short*)&ha, ub = *(unsigned short*)&hb;
    return (uint32_t)ua | ((uint32_t)ub << 16);
}
__device__ __forceinline__ uint32_t pack_bf16_rn(float a, float b) {
    __nv_bfloat162 p = __floats2bfloat162_rn(a, b);
    return *(uint32_t*)&p;
}

// ---------------- count: g_agg reset + degree count ----------------
__global__ void count_kernel(const int* __restrict__ ei) {
    int idx = blockIdx.x * blockDim.x + threadIdx.x;
    if (idx < SCAN_NB) g_agg[idx] = 0;
    if (idx < Ee / 4) {   // degree count (g_cnt zero by invariant)
        int4 d = __ldg((const int4*)(ei + Ee) + idx);
        atomicAdd(&g_cnt[d.x], 1);
        atomicAdd(&g_cnt[d.y], 1);
        atomicAdd(&g_cnt[d.z], 1);
        atomicAdd(&g_cnt[d.w], 1);
    }
}

// ---------------- single-pass scan (value-as-flag lookback; all 98 blocks co-resident) ----------------
__global__ void scan_kernel() {
    __shared__ int ws[16];
    __shared__ int ws2[4];
    __shared__ int s_off;
    int tid = threadIdx.x, lane = tid & 31, w = tid >> 5;
    int b = blockIdx.x;
    int i = b * 512 + tid;
    int v = (i < Nn) ? g_cnt[i] : 0;
    int x = v;
    #pragma unroll
    for (int off = 1; off < 32; off <<= 1) {
        int y = __shfl_up_sync(0xffffffffu, x, off);
        if (lane >= off) x += y;
    }
    if (lane == 31) ws[w] = x;
    __syncthreads();
    if (w == 0) {
        int t = (lane < 16) ? ws[lane] : 0;
        #pragma unroll
        for (int off = 1; off < 16; off <<= 1) {
            int y = __shfl_up_sync(0xffffffffu, t, off);
            if (lane >= off) t += y;
        }
        if (lane < 16) ws[lane] = t;
    }
    __syncthreads();
    // publish aggregate (value doubles as ready flag: total+1 >= 1)
    if (tid == 0) atomicExch((int*)&g_agg[b], ws[15] + 1);
    // lookback: sum aggregates of all predecessor blocks
    if (tid < 128) {
        int val = 0;
        if (tid < b) {
            int t;
            do { t = g_agg[tid]; } while (t == 0);
            val = t - 1;
        }
        #pragma unroll
        for (int off = 16; off > 0; off >>= 1)
            val += __shfl_xor_sync(0xffffffffu, val, off);
        if (lane == 0) ws2[w] = val;
    }
    __syncthreads();
    if (tid == 0) s_off = ws2[0] + ws2[1] + ws2[2] + ws2[3];
    __syncthreads();
    int excl = (w ? ws[w - 1] : 0) + x - v;
    if (i < Nn) g_rowptr[i] = s_off + excl;
    if (b == 0 && tid == 0) g_rowptr[Nn] = Ee;
}

// ---------------- scatter + piggybacked weight prep (fills atomic-latency idle slots) ----------------
__global__ void scatter_kernel(const int* __restrict__ ei,
                               const float* w0, const float* w1, const float* w2,
                               const float* w3, const float* w4, const float* w5,
                               const float* w6, const float* w7, const float* clsW) {
    int idx = blockIdx.x * blockDim.x + threadIdx.x;

    // piggyback: classifier tile (first 2048 threads)
    if (idx < 16 * DIM) {
        int n = idx >> 7, k = idx & 127;
        float v = 0.f;
        if (n < 6) v = clsW[k * NC + n];
        else if (n >= 8 && n < 14) v = clsW[(128 + k) * NC + (n - 8)];
        __nv_bfloat16 h = __float2bfloat16(v);
        g_W3hi[idx] = h;
        g_W3lo[idx] = __float2bfloat16(v - __bfloat162float(h));
    }
    // piggyback: weight split/transpose (first 131072 threads)
    if (idx < 8 * DIM * DIM) {
        const float* ws[8] = {w0, w1, w2, w3, w4, w5, w6, w7};
        int g = idx >> 14, e = idx & 16383;
        int n = e >> 7, k = e & 127;
        float v = ws[g][k * DIM + n];
        __nv_bfloat16 h = __float2bfloat16(v);
        g_Whi[g * 16384 + e] = h;
        g_Wlo[g * 16384 + e] = __float2bfloat16(v - __bfloat162float(h));
    }

    // scatter proper
    if (idx < Ee) {
        int d = ei[Ee + idx];
        int slot = atomicSub(&g_cnt[d], 1) - 1;   // counts -> 0 (self-restoring)
        g_neigh[g_rowptr[d] + slot] = ei[idx];
    }
}

// ---------------- aggregation: (xhi,xlo) = split(h[i] + sum_{j->i} h[j]), 8 loads in flight ----------------
__global__ void agg_kernel(const float* __restrict__ hin,
                           __nv_bfloat16* __restrict__ xhi,
                           __nv_bfloat16* __restrict__ xlo) {
    int w = (blockIdx.x * blockDim.x + threadIdx.x) >> 5;
    int lane = threadIdx.x & 31;
    if (w >= Nn) return;
    const float4* hp = (const float4*)hin;
    float4 a = __ldg(&hp[(size_t)w * 32 + lane]);
    float x0 = a.x, x1 = a.y, x2 = a.z, x3 = a.w;
    int beg = g_rowptr[w], end = g_rowptr[w + 1];
    int e = beg;
    for (; e + 7 < end; e += 8) {
        int j0 = g_neigh[e],     j1 = g_neigh[e + 1];
        int j2 = g_neigh[e + 2], j3 = g_neigh[e + 3];
        int j4 = g_neigh[e + 4], j5 = g_neigh[e + 5];
        int j6 = g_neigh[e + 6], j7 = g_neigh[e + 7];
        float4 v0 = __ldg(&hp[(size_t)j0 * 32 + lane]);
        float4 v1 = __ldg(&hp[(size_t)j1 * 32 + lane]);
        float4 v2 = __ldg(&hp[(size_t)j2 * 32 + lane]);
        float4 v3 = __ldg(&hp[(size_t)j3 * 32 + lane]);
        float4 v4 = __ldg(&hp[(size_t)j4 * 32 + lane]);
        float4 v5 = __ldg(&hp[(size_t)j5 * 32 + lane]);
        float4 v6 = __ldg(&hp[(size_t)j6 * 32 + lane]);
        float4 v7 = __ldg(&hp[(size_t)j7 * 32 + lane]);
        x0 += (v0.x + v1.x) + (v2.x + v3.x) + (v4.x + v5.x) + (v6.x + v7.x);
        x1 += (v0.y + v1.y) + (v2.y + v3.y) + (v4.y + v5.y) + (v6.y + v7.y);
        x2 += (v0.z + v1.z) + (v2.z + v3.z) + (v4.z + v5.z) + (v6.z + v7.z);
        x3 += (v0.w + v1.w) + (v2.w + v3.w) + (v4.w + v5.w) + (v6.w + v7.w);
    }
    for (; e + 1 < end; e += 2) {
        int j0 = g_neigh[e], j1 = g_neigh[e + 1];
        float4 v0 = __ldg(&hp[(size_t)j0 * 32 + lane]);
        float4 v1 = __ldg(&hp[(size_t)j1 * 32 + lane]);
        x0 += v0.x + v1.x; x1 += v0.y + v1.y;
        x2 += v0.z + v1.z; x3 += v0.w + v1.w;
    }
    if (e < end) {
        int j = g_neigh[e];
        float4 v = __ldg(&hp[(size_t)j * 32 + lane]);
        x0 += v.x; x1 += v.y; x2 += v.z; x3 += v.w;
    }
    float r0, r1, r2, r3;
    uint2 hw, lw;
    hw.x = pack_bf16(x0, x1, &r0, &r1);
    hw.y = pack_bf16(x2, x3, &r2, &r3);
    lw.x = pack_bf16_rn(r0, r1);
    lw.y = pack_bf16_rn(r2, r3);
    size_t off = (size_t)w * DIM + lane * 4;
    *(uint2*)(xhi + off) = hw;
    *(uint2*)(xlo + off) = lw;
}

// ---------------- fused dual-GEMM MLP (+ optional classifier MMA pass) ----------------
// MODE1 0: epilogue1 = BN+ReLU; 1: bias+ReLU.
// OUTBF 0: epilogue2 -> fp32 Hout; 1: -> split bf16 (Ohi/Olo).
// PQ 1: after epilogue2, run N=16 classifier MMA on final H, emit g_p/g_q.
template <int MODE1, int OUTBF, int PQ>
__global__ __launch_bounds__(512, 1) void fused_mlp(
    const __nv_bfloat16* __restrict__ Ahi_g, const __nv_bfloat16* __restrict__ Alo_g,
    const __nv_bfloat16* __restrict__ B1h, const __nv_bfloat16* __restrict__ B1l,
    const __nv_bfloat16* __restrict__ B2h, const __nv_bfloat16* __restrict__ B2l,
    const float* __restrict__ b1, const float* __restrict__ gg,
    const float* __restrict__ be, const float* __restrict__ rm,
    const float* __restrict__ rv, const float* __restrict__ b2,
    const float* __restrict__ clsb,
    float* __restrict__ Hout, __nv_bfloat16* __restrict__ Ohi,
    __nv_bfloat16* __restrict__ Olo, int M, int ntiles)
{
    extern __shared__ __align__(16) char dyn[];
    __shared__ float s_sc[DIM], s_sh[DIM], s_b2[DIM], s_cb[8];

    const int tid = threadIdx.x, lane = tid & 31, wid = tid >> 5;
    const uint32_t sbase = smem_u32(dyn);

    if (tid < DIM) {
        int c = tid;
        if (MODE1 == 0) {
            float s = gg[c] * rsqrtf(rv[c] + 1e-5f);
            s_sc[c] = s;
            s_sh[c] = (b1[c] - rm[c]) * s + be[c];
        } else {
            s_sc[c] = 1.0f;
            s_sh[c] = b1[c];
        }
        s_b2[c] = b2[c];
    }
    if (PQ && tid < 8) s_cb[tid] = (tid < 6) ? clsb[tid] : 0.f;

    {   // weight tiles once (persistent block)
        const uint4* p1h = (const uint4*)B1h;
        const uint4* p1l = (const uint4*)B1l;
        const uint4* p2h = (const uint4*)B2h;
        const uint4* p2l = (const uint4*)B2l;
        #pragma unroll
        for (int it = 0; it < 4; it++) {
            int i = tid + it * 512;
            uint32_t so = (uint32_t)(i >> 4) * TSTRIDE + (i & 15) * 16;
            *(uint4*)(dyn + 2 * TILE_BYTES + so) = __ldg(p1h + i);
            *(uint4*)(dyn + 3 * TILE_BYTES + so) = __ldg(p1l + i);
            *(uint4*)(dyn + 4 * TILE_BYTES + so) = __ldg(p2h + i);
            *(uint4*)(dyn + 5 * TILE_BYTES + so) = __ldg(p2l + i);
        }
        if (PQ && tid < 256) {   // classifier tile 16x128 bf16 hi/lo
            uint32_t so = (uint32_t)(tid >> 4) * TSTRIDE + (tid & 15) * 16;
            *(uint4*)(dyn + 6 * TILE_BYTES + so) = __ldg((const uint4*)g_W3hi + tid);
            *(uint4*)(dyn + 6 * TILE_BYTES + PQ_TILE + so) = __ldg((const uint4*)g_W3lo + tid);
        }
    }

    const int wm = wid >> 2, wn = wid & 3;
    const uint32_t aAddr = sbase + (uint32_t)(wm * 32 + (lane & 15)) * TSTRIDE + (lane >> 4) * 16;
    // B via ldsm4: lanes 0-7 -> [n0-7,klo], 8-15 -> [n0-7,khi], 16-23 -> [n8-15,klo], 24-31 -> [n8-15,khi]
    const int quad = lane >> 3;
    const uint32_t bRow = (uint32_t)((quad >> 1) * 8 + (lane & 7));
    const uint32_t bCol = (uint32_t)((quad & 1) * 16);
    const uint32_t bAddr1 = sbase + 2 * TILE_BYTES +
                            ((uint32_t)wn * 32 + bRow) * TSTRIDE + bCol;
    const uint32_t bAddr2 = bAddr1 + 2 * TILE_BYTES;
    const uint32_t bAddr3 = sbase + 6 * TILE_BYTES + bRow * TSTRIDE + bCol;
    const int g4 = lane >> 2, tig = lane & 3;
    // PQ warps: one per SMSP, one per wm band: wid 0,5,10,15
    const bool pqWarp = PQ && ((wid & 3) == (wid >> 2));

    for (int t = blockIdx.x; t < ntiles; t += gridDim.x) {
        int row0 = t * 128;
        __syncthreads();   // prior-tile readers of A smem done

        {   // A tiles: straight uint4 copies
            const uint4* ah4 = (const uint4*)(Ahi_g + (size_t)row0 * DIM);
            const uint4* al4 = (const uint4*)(Alo_g + (size_t)row0 * DIM);
            #pragma unroll
            for (int it = 0; it < 4; it++) {
                int i = tid + it * 512;
                uint32_t so = (uint32_t)(i >> 4) * TSTRIDE + (i & 15) * 16;
                *(uint4*)(dyn + so) = __ldg(ah4 + i);
                *(uint4*)(dyn + TILE_BYTES + so) = __ldg(al4 + i);
            }
        }
        __syncthreads();

        // ---- MMA pass 1 ----
        float acc[2][4][4];
        #pragma unroll
        for (int ma = 0; ma < 2; ma++)
            #pragma unroll
            for (int na = 0; na < 4; na++)
                #pragma unroll
                for (int q = 0; q < 4; q++) acc[ma][na][q] = 0.f;

        #pragma unroll
        for (int ks = 0; ks < 8; ks++) {
            uint32_t kb = ks * 32;
            uint32_t ah[2][4], al[2][4], bh[2][4], bl[2][4];
            ldsm4(ah[0], aAddr + kb);
            ldsm4(ah[1], aAddr + 16 * TSTRIDE + kb);
            ldsm4(al[0], aAddr + TILE_BYTES + kb);
            ldsm4(al[1], aAddr + TILE_BYTES + 16 * TSTRIDE + kb);
            ldsm4(bh[0], bAddr1 + kb);                         // n0-15: {r0,r1},{r2,r3}
            ldsm4(bh[1], bAddr1 + 16 * TSTRIDE + kb);          // n16-31
            ldsm4(bl[0], bAddr1 + TILE_BYTES + kb);
            ldsm4(bl[1], bAddr1 + TILE_BYTES + 16 * TSTRIDE + kb);
            #pragma unroll
            for (int ma = 0; ma < 2; ma++)
                #pragma unroll
                for (int na = 0; na < 4; na++) {
                    const uint32_t* pbh = &bh[na >> 1][(na & 1) * 2];
                    const uint32_t* pbl = &bl[na >> 1][(na & 1) * 2];
                    mma16816(acc[ma][na], ah[ma], pbh);
                    mma16816(acc[ma][na], ah[ma], pbl);
                    mma16816(acc[ma][na], al[ma], pbh);
                }
        }
        __syncthreads();   // all warps done reading A tile

        // epilogue 1: scale/shift + ReLU, split, Z -> A smem
        #pragma unroll
        for (int ma = 0; ma < 2; ma++) {
            int lr1 = wm * 32 + ma * 16 + g4;
            int lr2 = lr1 + 8;
            #pragma unroll
            for (int na = 0; na < 4; na++) {
                int col = wn * 32 + na * 8 + 2 * tig;
                float sc0 = s_sc[col], sc1 = s_sc[col + 1];
                float sh0 = s_sh[col], sh1 = s_sh[col + 1];
                float o0 = fmaxf(fmaf(acc[ma][na][0], sc0, sh0), 0.f);
                float o1 = fmaxf(fmaf(acc[ma][na][1], sc1, sh1), 0.f);
                float o2 = fmaxf(fmaf(acc[ma][na][2], sc0, sh0), 0.f);
                float o3 = fmaxf(fmaf(acc[ma][na][3], sc1, sh1), 0.f);
                float q0, q1;
                uint32_t so1 = (uint32_t)lr1 * TSTRIDE + col * 2;
                uint32_t so2 = (uint32_t)lr2 * TSTRIDE + col * 2;
                *(uint32_t*)(dyn + so1) = pack_bf16(o0, o1, &q0, &q1);
                *(uint32_t*)(dyn + TILE_BYTES + so1) = pack_bf16_rn(q0, q1);
                *(uint32_t*)(dyn + so2) = pack_bf16(o2, o3, &q0, &q1);
                *(uint32_t*)(dyn + TILE_BYTES + so2) = pack_bf16_rn(q0, q1);
            }
        }
        __syncthreads();

        // ---- MMA pass 2 ----
        #pragma unroll
        for (int ma = 0; ma < 2; ma++)
            #pragma unroll
            for (int na = 0; na < 4; na++)
                #pragma unroll
                for (int q = 0; q < 4; q++) acc[ma][na][q] = 0.f;

        #pragma unroll
        for (int ks = 0; ks < 8; ks++) {
            uint32_t kb = ks * 32;
            uint32_t ah[2][4], al[2][4], bh[2][4], bl[2][4];
            ldsm4(ah[0], aAddr + kb);
            ldsm4(ah[1], aAddr + 16 * TSTRIDE + kb);
            ldsm4(al[0], aAddr + TILE_BYTES + kb);
            ldsm4(al[1], aAddr + TILE_BYTES + 16 * TSTRIDE + kb);
            ldsm4(bh[0], bAddr2 + kb);
            ldsm4(bh[1], bAddr2 + 16 * TSTRIDE + kb);
            ldsm4(bl[0], bAddr2 + TILE_BYTES + kb);
            ldsm4(bl[1], bAddr2 + TILE_BYTES + 16 * TSTRIDE + kb);
            #pragma unroll
            for (int ma = 0; ma < 2; ma++)
                #pragma unroll
                for (int na = 0; na < 4; na++) {
                    const uint32_t* pbh = &bh[na >> 1][(na & 1) * 2];
                    const uint32_t* pbl = &bl[na >> 1][(na & 1) * 2];
                    mma16816(acc[ma][na], ah[ma], pbh);
                    mma16816(acc[ma][na], ah[ma], pbl);
                    mma16816(acc[ma][na], al[ma], pbh);
                }
        }
        if (PQ) __syncthreads();   // all warps done reading Z before H-split overwrites it

        // epilogue 2: bias + ReLU -> fp32 / split bf16; PQ: also H-split -> A smem
        #pragma unroll
        for (int ma = 0; ma < 2; ma++) {
            int r1 = row0 + wm * 32 + ma * 16 + g4;
            int r2 = r1 + 8;
            int lr1 = wm * 32 + ma * 16 + g4;
            int lr2 = lr1 + 8;
            #pragma unroll
            for (int na = 0; na < 4; na++) {
                int col = wn * 32 + na * 8 + 2 * tig;
                float sh0 = s_b2[col], sh1 = s_b2[col + 1];
                float o0 = fmaxf(acc[ma][na][0] + sh0, 0.f);
                float o1 = fmaxf(acc[ma][na][1] + sh1, 0.f);
                float o2 = fmaxf(acc[ma][na][2] + sh0, 0.f);
                float o3 = fmaxf(acc[ma][na][3] + sh1, 0.f);
                if (PQ) {
                    float q0, q1;
                    uint32_t so1 = (uint32_t)lr1 * TSTRIDE + col * 2;
                    uint32_t so2 = (uint32_t)lr2 * TSTRIDE + col * 2;
                    *(uint32_t*)(dyn + so1) = pack_bf16(o0, o1, &q0, &q1);
                    *(uint32_t*)(dyn + TILE_BYTES + so1) = pack_bf16_rn(q0, q1);
                    *(uint32_t*)(dyn + so2) = pack_bf16(o2, o3, &q0, &q1);
                    *(uint32_t*)(dyn + TILE_BYTES + so2) = pack_bf16_rn(q0, q1);
                }
                if (OUTBF) {
                    if (r1 < M) {
                        float q0, q1;
                        *(uint32_t*)(Ohi + (size_t)r1 * DIM + col) = pack_bf16(o0, o1, &q0, &q1);
                        *(uint32_t*)(Olo + (size_t)r1 * DIM + col) = pack_bf16_rn(q0, q1);
                    }
                    if (r2 < M) {
                        float q0, q1;
                        *(uint32_t*)(Ohi + (size_t)r2 * DIM + col) = pack_bf16(o2, o3, &q0, &q1);
                        *(uint32_t*)(Olo + (size_t)r2 * DIM + col) = pack_bf16_rn(q0, q1);
                    }
                } else {
                    if (r1 < M) *(float2*)(Hout + (size_t)r1 * DIM + col) = make_float2(o0, o1);
                    if (r2 < M) *(float2*)(Hout + (size_t)r2 * DIM + col) = make_float2(o2, o3);
                }
            }
        }

        if (PQ) {
            __syncthreads();   // H-split visible
            if (pqWarp) {
                float acc3[2][2][4];
                #pragma unroll
                for (int ma = 0; ma < 2; ma++)
                    #pragma unroll
                    for (int na = 0; na < 2; na++)
                        #pragma unroll
                        for (int q = 0; q < 4; q++) acc3[ma][na][q] = 0.f;
                #pragma unroll
                for (int ks = 0; ks < 8; ks++) {
                    uint32_t kb = ks * 32;
                    uint32_t ah[2][4], al[2][4], b3h[4], b3l[4];
                    ldsm4(ah[0], aAddr + kb);
                    ldsm4(ah[1], aAddr + 16 * TSTRIDE + kb);
                    ldsm4(al[0], aAddr + TILE_BYTES + kb);
                    ldsm4(al[1], aAddr + TILE_BYTES + 16 * TSTRIDE + kb);
                    ldsm4(b3h, bAddr3 + kb);            // {r0,r1}=p rows, {r2,r3}=q rows
                    ldsm4(b3l, bAddr3 + PQ_TILE + kb);
                    #pragma unroll
                    for (int ma = 0; ma < 2; ma++)
                        #pragma unroll
                        for (int na = 0; na < 2; na++) {
                            const uint32_t* pbh = &b3h[na * 2];
                            const uint32_t* pbl = &b3l[na * 2];
                            mma16816(acc3[ma][na], ah[ma], pbh);
                            mma16816(acc3[ma][na], ah[ma], pbl);
                            mma16816(acc3[ma][na], al[ma], pbh);
                        }
                }
                // emit p (na=0, +bias) and q (na=1)
                #pragma unroll
                for (int ma = 0; ma < 2; ma++) {
                    int r1 = row0 + wm * 32 + ma * 16 + g4;
                    int r2 = r1 + 8;
                    int c0 = 2 * tig;
                    if (r1 < M) {
                        *(float2*)(g_p + (size_t)r1 * 8 + c0) =
                            make_float2(acc3[ma][0][0] + s_cb[c0], acc3[ma][0][1] + s_cb[c0 + 1]);
                        *(float2*)(g_q + (size_t)r1 * 8 + c0) =
                            make_float2(acc3[ma][1][0], acc3[ma][1][1]);
                    }
                    if (r2 < M) {
                        *(float2*)(g_p + (size_t)r2 * 8 + c0) =
                            make_float2(acc3[ma][0][2] + s_cb[c0], acc3[ma][0][3] + s_cb[c0 + 1]);
                        *(float2*)(g_q + (size_t)r2 * 8 + c0) =
                            make_float2(acc3[ma][1][2], acc3[ma][1][3]);
                    }
                }
            }
        }
    }
}

// ---------------- final: 8 edges per warp (MLP=16 row loads, 8KB contiguous stores) ----------------
__global__ void final_kernel(const float* __restrict__ h, const int* __restrict__ ei,
                             float* __restrict__ out0, float* __restrict__ eout) {
    int w = (blockIdx.x * blockDim.x + threadIdx.x) >> 5;
    int lane = threadIdx.x & 31;
    int e0 = w << 3;
    if (e0 >= Ee) return;
    const float4* hp = (const float4*)h;
    int s[8], d[8];
    #pragma unroll
    for (int i = 0; i < 8; i++) {
        s[i] = __ldg(ei + e0 + i);
        d[i] = __ldg(ei + Ee + e0 + i);
    }
    float4 av[8], bv[8];
    #pragma unroll
    for (int i = 0; i < 8; i++) {
        av[i] = __ldg(&hp[(size_t)s[i] * 32 + lane]);
        bv[i] = __ldg(&hp[(size_t)d[i] * 32 + lane]);
    }
    float4* ep = (float4*)(eout + (size_t)e0 * 256);
    #pragma unroll
    for (int i = 0; i < 8; i++) {
        __stcs(&ep[i * 64 + lane], av[i]);
        __stcs(&ep[i * 64 + 32 + lane], bv[i]);
    }
    if (lane < NC) {
        #pragma unroll
        for (int i = 0; i < 8; i++)
            __stcs(&out0[(size_t)(e0 + i) * NC + lane],
                   g_p[s[i] * 8 + lane] + g_q[d[i] * 8 + lane]);
    }
}

// ---------------- launch ----------------
extern "C" void kernel_launch(void* const* d_in, const int* in_sizes, int n_in,
                              void* d_out, int out_size) {
    const float* x     = (const float*)d_in[0];
    const int*   ei    = (const int*)d_in[1];
    const float* c1_W1 = (const float*)d_in[3];
    const float* c1_b1 = (const float*)d_in[4];
    const float* c1_g  = (const float*)d_in[5];
    const float* c1_be = (const float*)d_in[6];
    const float* c1_rm = (const float*)d_in[7];
    const float* c1_rv = (const float*)d_in[8];
    const float* c1_W2 = (const float*)d_in[9];
    const float* c1_b2 = (const float*)d_in[10];
    const float* cv_W1 = (const float*)d_in[11];
    const float* cv_b1 = (const float*)d_in[12];
    const float* cv_g  = (const float*)d_in[13];
    const float* cv_be = (const float*)d_in[14];
    const float* cv_rm = (const float*)d_in[15];
    const float* cv_rv = (const float*)d_in[16];
    const float* cv_W2 = (const float*)d_in[17];
    const float* cv_b2 = (const float*)d_in[18];
    const float* lin_W = (const float*)d_in[19];
    const float* lin_b = (const float*)d_in[20];
    const float* cls_W = (const float*)d_in[21];
    const float* cls_b = (const float*)d_in[22];

    float* out0 = (float*)d_out;
    float* eout = out0 + (size_t)Ee * NC;

    void *ph, *pxh, *pxl, *px2h, *px2l, *pwh, *pwl;
    cudaGetSymbolAddress(&ph, g_h);
    cudaGetSymbolAddress(&pxh, g_xhi);
    cudaGetSymbolAddress(&pxl, g_xlo);
    cudaGetSymbolAddress(&px2h, g_x2hi);
    cudaGetSymbolAddress(&px2l, g_x2lo);
    cudaGetSymbolAddress(&pwh, g_Whi);
    cudaGetSymbolAddress(&pwl, g_Wlo);
    float* H = (float*)ph;
    __nv_bfloat16* XH = (__nv_bfloat16*)pxh;
    __nv_bfloat16* XL = (__nv_bfloat16*)pxl;
    __nv_bfloat16* X2H = (__nv_bfloat16*)px2h;
    __nv_bfloat16* X2L = (__nv_bfloat16*)px2l;
    const __nv_bfloat16* WH = (const __nv_bfloat16*)pwh;
    const __nv_bfloat16* WL = (const __nv_bfloat16*)pwl;

    const int NT = Nn2 / 128;                 // 391 tiles
    const int GG = 148;
    const int AGG_B = (Nn * 32 + 255) / 256;          // 1 node per warp
    const int FIN_B = ((Ee / 8) * 32 + 255) / 256;    // 8 edges per warp
    const int SMEM_F  = 6 * TILE_BYTES;               // 208896
    const int SMEM_FP = 6 * TILE_BYTES + 2 * PQ_TILE; // 217600

    cudaFuncSetAttribute(fused_mlp<0, 0, 0>, cudaFuncAttributeMaxDynamicSharedMemorySize, SMEM_F);
    cudaFuncSetAttribute(fused_mlp<0, 1, 0>, cudaFuncAttributeMaxDynamicSharedMemorySize, SMEM_F);
    cudaFuncSetAttribute(fused_mlp<1, 0, 1>, cudaFuncAttributeMaxDynamicSharedMemorySize, SMEM_FP);

    // CSR build; weight prep piggybacked on scatter
    count_kernel<<<625, 256>>>(ei);
    scan_kernel<<<SCAN_NB, 512>>>();
    scatter_kernel<<<(Ee + 255) / 256, 256>>>(ei, c1_W1, c1_W2,
                                              cv_W1, cv_W1 + DIM * DIM,
                                              cv_W2, cv_W2 + DIM * DIM,
                                              lin_W, lin_W + DIM * DIM, cls_W);
    // slots: 0=c1_W1 1=c1_W2 2=cvW1[0] 3=cvW1[1] 4=cvW2[0] 5=cvW2[1] 6=linW[0] 7=linW[1]

    // GIN1: agg(x) -> X; MLP(X) -> H
    agg_kernel<<<AGG_B, 256>>>(x, XH, XL);
    fused_mlp<0, 0, 0><<<GG, 512, SMEM_F>>>(XH, XL, WH + 0 * 16384, WL + 0 * 16384,
                                            WH + 1 * 16384, WL + 1 * 16384,
                                            c1_b1, c1_g, c1_be, c1_rm, c1_rv, c1_b2, 0,
                                            H, 0, 0, Nn, NT);
    // GIN2
    agg_kernel<<<AGG_B, 256>>>(H, XH, XL);
    fused_mlp<0, 0, 0><<<GG, 512, SMEM_F>>>(XH, XL, WH + 2 * 16384, WL + 2 * 16384,
                                            WH + 4 * 16384, WL + 4 * 16384,
                                            cv_b1, cv_g, cv_be, cv_rm, cv_rv, cv_b2, 0,
                                            H, 0, 0, Nn, NT);
    // GIN3 -> split X2
    agg_kernel<<<AGG_B, 256>>>(H, XH, XL);
    fused_mlp<0, 1, 0><<<GG, 512, SMEM_F>>>(XH, XL, WH + 3 * 16384, WL + 3 * 16384,
                                            WH + 5 * 16384, WL + 5 * 16384,
                                            cv_b1 + DIM, cv_g + DIM, cv_be + DIM,
                                            cv_rm + DIM, cv_rv + DIM, cv_b2 + DIM, 0,
                                            0, X2H, X2L, Nn, NT);
    // linear layers + fused classifier: MLP(X2) -> H, p, q
    fused_mlp<1, 0, 1><<<GG, 512, SMEM_FP>>>(X2H, X2L, WH + 6 * 16384, WL + 6 * 16384,
                                             WH + 7 * 16384, WL + 7 * 16384,
                                             lin_b, 0, 0, 0, 0, lin_b + DIM, cls_b,
                                             H, 0, 0, Nn, NT);

    // edge output (edge-ordered, 8 edges/warp)
    final_kernel<<<FIN_B, 256>>>(H, ei, out0, eout);
}